// round 2
// baseline (speedup 1.0000x reference)
#include <cuda_runtime.h>

#define B_  4
#define S_  2048
#define TD  768
#define HID 512
#define NH  8
#define HD  64
#define VD  768
#define M_  (B_*S_)   // 8192

// Scratch (allocation-free rule: __device__ globals)
__device__ float g_q[B_*NH*S_*HD];
__device__ float g_k[B_*NH*S_*HD];
__device__ float g_v[B_*NH*S_*HD];
__device__ float g_att[M_*HID];

// ---------------------------------------------------------------------------
// QKV projection: Y = X[8192,768] * W[768,512] + b, written head-major:
// out[((b*8+h)*2048+s)*64+d]   (grid.z selects q/k/v)
// ---------------------------------------------------------------------------
__global__ __launch_bounds__(256) void gemm_qkv(
    const float* __restrict__ X,
    const float* __restrict__ Wq, const float* __restrict__ Bq,
    const float* __restrict__ Wk, const float* __restrict__ Bk,
    const float* __restrict__ Wv, const float* __restrict__ Bv)
{
    __shared__ float As[8][128];
    __shared__ float Bs[8][128];

    const float* W; const float* bias; float* out;
    if (blockIdx.z == 0)      { W = Wq; bias = Bq; out = g_q; }
    else if (blockIdx.z == 1) { W = Wk; bias = Bk; out = g_k; }
    else                      { W = Wv; bias = Bv; out = g_v; }

    const int tid = threadIdx.x;
    const int ty = tid >> 4, tx = tid & 15;
    const int rowBase = blockIdx.y * 128;
    const int colBase = blockIdx.x * 128;

    float acc[8][8];
#pragma unroll
    for (int i = 0; i < 8; i++)
#pragma unroll
        for (int j = 0; j < 8; j++) acc[i][j] = 0.f;

    const int arow = tid >> 1, aseg = tid & 1;       // A: 128 rows x 8 k, float4
    const int brow = tid >> 5, bc4  = tid & 31;      // B: 8 k x 128 n, float4

    for (int k0 = 0; k0 < TD; k0 += 8) {
        float4 a = *(const float4*)&X[(size_t)(rowBase + arow) * TD + k0 + aseg * 4];
        As[aseg*4+0][arow] = a.x; As[aseg*4+1][arow] = a.y;
        As[aseg*4+2][arow] = a.z; As[aseg*4+3][arow] = a.w;
        float4 bv = *(const float4*)&W[(size_t)(k0 + brow) * HID + colBase + bc4 * 4];
        *(float4*)&Bs[brow][bc4 * 4] = bv;
        __syncthreads();
#pragma unroll
        for (int k = 0; k < 8; k++) {
            float ra[8], rb[8];
#pragma unroll
            for (int i = 0; i < 8; i++) ra[i] = As[k][ty * 8 + i];
#pragma unroll
            for (int j = 0; j < 8; j++) rb[j] = Bs[k][tx * 8 + j];
#pragma unroll
            for (int i = 0; i < 8; i++)
#pragma unroll
                for (int j = 0; j < 8; j++) acc[i][j] += ra[i] * rb[j];
        }
        __syncthreads();
    }

#pragma unroll
    for (int i = 0; i < 8; i++) {
        const int m = rowBase + ty * 8 + i;
        const int b = m >> 11, s = m & 2047;
#pragma unroll
        for (int j = 0; j < 8; j++) {
            const int n = colBase + tx * 8 + j;
            const int h = n >> 6, d = n & 63;
            out[(((size_t)(b * NH + h) * S_) + s) * HD + d] = acc[i][j] + bias[n];
        }
    }
}

// ---------------------------------------------------------------------------
// Attention: one block = one (b,h) head + 16 query rows.
// Full 16x2048 fp32 score rows in dynamic smem; K/V tiles padded to stride 65.
// ---------------------------------------------------------------------------
#define KPAD 65
#define ATT_SMEM_FLOATS (16*HD + 128*KPAD + 16*S_)

__global__ __launch_bounds__(256) void attn_kernel()
{
    extern __shared__ float sm[];
    float* sQ = sm;                    // 16 x 64
    float* sK = sm + 16 * HD;          // 128 x 65  (K tile, then reused for V)
    float* sS = sK + 128 * KPAD;       // 16 x 2048

    const int tid = threadIdx.x;
    const int hb = blockIdx.y;
    const int b = hb >> 3, h = hb & 7;
    const int qs = blockIdx.x * 16;

    const size_t headOff = (size_t)(b * NH + h) * S_ * HD;
    const float* Q = g_q + headOff;
    const float* K = g_k + headOff;
    const float* V = g_v + headOff;

    // load Q tile: 16 rows x 16 float4 per row = 256 float4  (FIXED mapping)
    {
        const int row = tid >> 4, seg = tid & 15;
        float4 qv = *(const float4*)&Q[(size_t)(qs + row) * HD + seg * 4];
        *(float4*)&sQ[row * HD + seg * 4] = qv;
    }
    __syncthreads();

    const int ty = tid >> 4, tx = tid & 15;
    const float scale = 0.125f;   // 1/sqrt(64)

    // ---- phase 1: scores ----
    for (int kt = 0; kt < 16; kt++) {
#pragma unroll
        for (int it = 0; it < 8; it++) {
            const int idx = it * 256 + tid;           // 2048 float4
            const int row = idx >> 4, c4 = idx & 15;
            float4 kv = *(const float4*)&K[(size_t)(kt * 128 + row) * HD + c4 * 4];
            float* dst = &sK[row * KPAD + c4 * 4];
            dst[0] = kv.x; dst[1] = kv.y; dst[2] = kv.z; dst[3] = kv.w;
        }
        __syncthreads();

        float acc[8];
#pragma unroll
        for (int j = 0; j < 8; j++) acc[j] = 0.f;
        const float* qrow = &sQ[ty * HD];
#pragma unroll 4
        for (int kk = 0; kk < HD; kk++) {
            const float qv = qrow[kk];
#pragma unroll
            for (int j = 0; j < 8; j++)
                acc[j] += qv * sK[(j * 16 + tx) * KPAD + kk];
        }
#pragma unroll
        for (int j = 0; j < 8; j++)
            sS[ty * S_ + kt * 128 + j * 16 + tx] = acc[j] * scale;
        __syncthreads();
    }

    // ---- phase 2: softmax (row ty shared by 16 lanes tx) ----
    {
        float mx = -1e30f;
        for (int i = tx; i < S_; i += 16) mx = fmaxf(mx, sS[ty * S_ + i]);
#pragma unroll
        for (int o = 8; o >= 1; o >>= 1) mx = fmaxf(mx, __shfl_xor_sync(0xffffffffu, mx, o));
        float sum = 0.f;
        for (int i = tx; i < S_; i += 16) {
            float e = __expf(sS[ty * S_ + i] - mx);
            sS[ty * S_ + i] = e;
            sum += e;
        }
#pragma unroll
        for (int o = 8; o >= 1; o >>= 1) sum += __shfl_xor_sync(0xffffffffu, sum, o);
        const float inv = 1.f / sum;
        for (int i = tx; i < S_; i += 16) sS[ty * S_ + i] *= inv;
    }
    __syncthreads();

    // ---- phase 3: O = P * V ; thread owns row ty, dims d = tx + 16u ----
    float o0 = 0.f, o1 = 0.f, o2 = 0.f, o3 = 0.f;
    for (int vt = 0; vt < 16; vt++) {
#pragma unroll
        for (int it = 0; it < 8; it++) {
            const int idx = it * 256 + tid;
            const int row = idx >> 4, c4 = idx & 15;
            float4 vv = *(const float4*)&V[(size_t)(vt * 128 + row) * HD + c4 * 4];
            float* dst = &sK[row * KPAD + c4 * 4];
            dst[0] = vv.x; dst[1] = vv.y; dst[2] = vv.z; dst[3] = vv.w;
        }
        __syncthreads();
#pragma unroll 4
        for (int c = 0; c < 128; c++) {
            const float p = sS[ty * S_ + vt * 128 + c];
            const float* vrow = &sK[c * KPAD + tx];
            o0 += p * vrow[0];
            o1 += p * vrow[16];
            o2 += p * vrow[32];
            o3 += p * vrow[48];
        }
        __syncthreads();
    }

    float* dst = &g_att[((size_t)(b * S_ + qs + ty)) * HID + h * HD + tx];
    dst[0]  = o0;
    dst[16] = o1;
    dst[32] = o2;
    dst[48] = o3;
}

// ---------------------------------------------------------------------------
// Output projection: out = att[8192,512] * Wo[512,768] + bo
// ---------------------------------------------------------------------------
__global__ __launch_bounds__(256) void gemm_out(
    const float* __restrict__ Wo, const float* __restrict__ bo,
    float* __restrict__ out)
{
    __shared__ float As[8][128];
    __shared__ float Bs[8][128];

    const int tid = threadIdx.x;
    const int ty = tid >> 4, tx = tid & 15;
    const int rowBase = blockIdx.y * 128;
    const int colBase = blockIdx.x * 128;

    float acc[8][8];
#pragma unroll
    for (int i = 0; i < 8; i++)
#pragma unroll
        for (int j = 0; j < 8; j++) acc[i][j] = 0.f;

    const int arow = tid >> 1, aseg = tid & 1;
    const int brow = tid >> 5, bc4  = tid & 31;

    for (int k0 = 0; k0 < HID; k0 += 8) {
        float4 a = *(const float4*)&g_att[(size_t)(rowBase + arow) * HID + k0 + aseg * 4];
        As[aseg*4+0][arow] = a.x; As[aseg*4+1][arow] = a.y;
        As[aseg*4+2][arow] = a.z; As[aseg*4+3][arow] = a.w;
        float4 bv = *(const float4*)&Wo[(size_t)(k0 + brow) * VD + colBase + bc4 * 4];
        *(float4*)&Bs[brow][bc4 * 4] = bv;
        __syncthreads();
#pragma unroll
        for (int k = 0; k < 8; k++) {
            float ra[8], rb[8];
#pragma unroll
            for (int i = 0; i < 8; i++) ra[i] = As[k][ty * 8 + i];
#pragma unroll
            for (int j = 0; j < 8; j++) rb[j] = Bs[k][tx * 8 + j];
#pragma unroll
            for (int i = 0; i < 8; i++)
#pragma unroll
                for (int j = 0; j < 8; j++) acc[i][j] += ra[i] * rb[j];
        }
        __syncthreads();
    }

#pragma unroll
    for (int i = 0; i < 8; i++) {
        const int m = rowBase + ty * 8 + i;
#pragma unroll
        for (int j = 0; j < 8; j++) {
            const int n = colBase + tx * 8 + j;
            out[(size_t)m * VD + n] = acc[i][j] + bo[n];
        }
    }
}

// ---------------------------------------------------------------------------
extern "C" void kernel_launch(void* const* d_in, const int* in_sizes, int n_in,
                              void* d_out, int out_size)
{
    const float* X  = (const float*)d_in[0];
    const float* Wq = (const float*)d_in[1];
    const float* bq = (const float*)d_in[2];
    const float* Wk = (const float*)d_in[3];
    const float* bk = (const float*)d_in[4];
    const float* Wv = (const float*)d_in[5];
    const float* bv = (const float*)d_in[6];
    const float* Wo = (const float*)d_in[7];
    const float* bo = (const float*)d_in[8];
    float* out = (float*)d_out;

    const size_t attn_smem = ATT_SMEM_FLOATS * sizeof(float);  // ~168 KB
    cudaFuncSetAttribute(attn_kernel, cudaFuncAttributeMaxDynamicSharedMemorySize,
                         (int)attn_smem);

    // 1) QKV projections
    {
        dim3 grid(HID / 128, M_ / 128, 3);
        gemm_qkv<<<grid, 256>>>(X, Wq, bq, Wk, bk, Wv, bv);
    }
    // 2) attention
    {
        dim3 grid(S_ / 16, B_ * NH);
        attn_kernel<<<grid, 256, attn_smem>>>();
    }
    // 3) output projection
    {
        dim3 grid(VD / 128, M_ / 128);
        gemm_out<<<grid, 256>>>(Wo, bo, out);
    }
}

// round 3
// speedup vs baseline: 2.2345x; 2.2345x over previous
#include <cuda_runtime.h>

#define B_  4
#define S_  2048
#define TD  768
#define HID 512
#define NH  8
#define HD  64
#define VD  768
#define M_  (B_*S_)   // 8192

// Scratch (allocation-free rule: __device__ globals)
__device__ float g_q[B_*NH*S_*HD];
__device__ float g_k[B_*NH*S_*HD];
__device__ float g_v[B_*NH*S_*HD];
__device__ float g_att[M_*HID];

// ---------------------------------------------------------------------------
// QKV projection: Y = X[8192,768] * W[768,512] + b, written head-major:
// out[((b*8+h)*2048+s)*64+d]   (grid.z selects q/k/v)
// ---------------------------------------------------------------------------
__global__ __launch_bounds__(256) void gemm_qkv(
    const float* __restrict__ X,
    const float* __restrict__ Wq, const float* __restrict__ Bq,
    const float* __restrict__ Wk, const float* __restrict__ Bk,
    const float* __restrict__ Wv, const float* __restrict__ Bv)
{
    __shared__ float As[8][128];
    __shared__ float Bs[8][128];

    const float* W; const float* bias; float* out;
    if (blockIdx.z == 0)      { W = Wq; bias = Bq; out = g_q; }
    else if (blockIdx.z == 1) { W = Wk; bias = Bk; out = g_k; }
    else                      { W = Wv; bias = Bv; out = g_v; }

    const int tid = threadIdx.x;
    const int ty = tid >> 4, tx = tid & 15;
    const int rowBase = blockIdx.y * 128;
    const int colBase = blockIdx.x * 128;

    float acc[8][8];
#pragma unroll
    for (int i = 0; i < 8; i++)
#pragma unroll
        for (int j = 0; j < 8; j++) acc[i][j] = 0.f;

    const int arow = tid >> 1, aseg = tid & 1;       // A: 128 rows x 8 k, float4
    const int brow = tid >> 5, bc4  = tid & 31;      // B: 8 k x 128 n, float4

    for (int k0 = 0; k0 < TD; k0 += 8) {
        float4 a = *(const float4*)&X[(size_t)(rowBase + arow) * TD + k0 + aseg * 4];
        As[aseg*4+0][arow] = a.x; As[aseg*4+1][arow] = a.y;
        As[aseg*4+2][arow] = a.z; As[aseg*4+3][arow] = a.w;
        float4 bv = *(const float4*)&W[(size_t)(k0 + brow) * HID + colBase + bc4 * 4];
        *(float4*)&Bs[brow][bc4 * 4] = bv;
        __syncthreads();
#pragma unroll
        for (int k = 0; k < 8; k++) {
            float ra[8], rb[8];
#pragma unroll
            for (int i = 0; i < 8; i++) ra[i] = As[k][ty * 8 + i];
#pragma unroll
            for (int j = 0; j < 8; j++) rb[j] = Bs[k][tx * 8 + j];
#pragma unroll
            for (int i = 0; i < 8; i++)
#pragma unroll
                for (int j = 0; j < 8; j++) acc[i][j] += ra[i] * rb[j];
        }
        __syncthreads();
    }

#pragma unroll
    for (int i = 0; i < 8; i++) {
        const int m = rowBase + ty * 8 + i;
        const int b = m >> 11, s = m & 2047;
#pragma unroll
        for (int j = 0; j < 8; j++) {
            const int n = colBase + tx * 8 + j;
            const int h = n >> 6, d = n & 63;
            out[(((size_t)(b * NH + h) * S_) + s) * HD + d] = acc[i][j] + bias[n];
        }
    }
}

// ---------------------------------------------------------------------------
// Flash-style attention: block = one (b,h) head x 128 query rows.
// Streams 16 key-tiles of 128; online softmax; register-tiled GEMMs.
//   S^T[key][q] = K * Q^T  (8x8/thread), softmax over key (cross-ty reduce),
//   O[q][d]    += P^T_col * V (8x4/thread).
// ---------------------------------------------------------------------------
#define QT 128
#define KT 128
#define QTP 132   // sQt row pad (floats)
#define KVP 68    // sK/sV row pad
#define PTP 132   // sPt row pad
#define RDP 132   // sRed row pad

#define OFF_QT  0
#define OFF_K   (OFF_QT + 64*QTP)           // 8448
#define OFF_V   (OFF_K + KT*KVP)            // +8704
#define OFF_PT  (OFF_V + KT*KVP)            // +8704
#define OFF_RED (OFF_PT + KT*PTP)           // +16896
#define OFF_M   (OFF_RED + 16*RDP)          // +2112
#define OFF_L   (OFF_M + QT)
#define OFF_SC  (OFF_L + QT)
#define ATT2_SMEM_FLOATS (OFF_SC + QT)

__global__ __launch_bounds__(256, 1) void attn_kernel2()
{
    extern __shared__ float sm[];
    float* sQt  = sm + OFF_QT;   // [64][QTP]  Qt[d][q] * 0.125
    float* sK   = sm + OFF_K;    // [128][KVP] K[key][d]
    float* sV   = sm + OFF_V;    // [128][KVP] V[key][d]
    float* sPt  = sm + OFF_PT;   // [128][PTP] P[key][q]
    float* sRed = sm + OFF_RED;  // [16][RDP]
    float* sM   = sm + OFF_M;    // [128] running max per q
    float* sL   = sm + OFF_L;    // [128] running sum per q
    float* sSc  = sm + OFF_SC;   // [128] rescale per q per tile

    const int tid = threadIdx.x;
    const int ty = tid >> 4, tx = tid & 15;
    const int hb = blockIdx.y;
    const int b = hb >> 3, h = hb & 7;
    const int qs = blockIdx.x * QT;

    const size_t headOff = (size_t)(b * NH + h) * S_ * HD;
    const float* Q = g_q + headOff;
    const float* K = g_k + headOff;
    const float* V = g_v + headOff;

    // ---- one-time: load Q tile transposed + pre-scaled ----
#pragma unroll
    for (int it = 0; it < 8; it++) {
        const int idx = it * 256 + tid;        // 2048 float4 = 128 rows x 16
        const int row = idx >> 4, c4 = idx & 15;
        float4 qv = *(const float4*)&Q[(size_t)(qs + row) * HD + c4 * 4];
        sQt[(c4*4+0)*QTP + row] = qv.x * 0.125f;
        sQt[(c4*4+1)*QTP + row] = qv.y * 0.125f;
        sQt[(c4*4+2)*QTP + row] = qv.z * 0.125f;
        sQt[(c4*4+3)*QTP + row] = qv.w * 0.125f;
    }
    if (tid < QT) { sM[tid] = -1e30f; sL[tid] = 0.f; }

    float o[8][4];
#pragma unroll
    for (int i = 0; i < 8; i++)
#pragma unroll
        for (int n = 0; n < 4; n++) o[i][n] = 0.f;

    __syncthreads();

    for (int kt = 0; kt < S_ / KT; kt++) {
        // ---- load K & V tiles (natural layout, padded rows) ----
#pragma unroll
        for (int it = 0; it < 8; it++) {
            const int idx = it * 256 + tid;
            const int row = idx >> 4, c4 = idx & 15;
            float4 kv = *(const float4*)&K[(size_t)(kt * KT + row) * HD + c4 * 4];
            *(float4*)&sK[row * KVP + c4 * 4] = kv;
            float4 vv = *(const float4*)&V[(size_t)(kt * KT + row) * HD + c4 * 4];
            *(float4*)&sV[row * KVP + c4 * 4] = vv;
        }
        __syncthreads();

        // ---- S^T tile: acc[i][j] = sum_d K[ty*8+i][d] * Qt[d][tx*8+j] ----
        float acc[8][8];
#pragma unroll
        for (int i = 0; i < 8; i++)
#pragma unroll
            for (int j = 0; j < 8; j++) acc[i][j] = 0.f;

#pragma unroll 4
        for (int k = 0; k < HD; k++) {
            float ra[8], rb[8];
#pragma unroll
            for (int i = 0; i < 8; i++) ra[i] = sK[(ty*8+i) * KVP + k];  // broadcast
            *(float4*)&rb[0] = *(const float4*)&sQt[k * QTP + tx*8];
            *(float4*)&rb[4] = *(const float4*)&sQt[k * QTP + tx*8 + 4];
#pragma unroll
            for (int i = 0; i < 8; i++)
#pragma unroll
                for (int j = 0; j < 8; j++) acc[i][j] += ra[i] * rb[j];
        }

        // ---- softmax step 1: column (per-q) max across ty ----
        {
            float lm[8];
#pragma unroll
            for (int j = 0; j < 8; j++) {
                float m = acc[0][j];
#pragma unroll
                for (int i = 1; i < 8; i++) m = fmaxf(m, acc[i][j]);
                lm[j] = m;
            }
#pragma unroll
            for (int j = 0; j < 8; j++) sRed[ty * RDP + tx*8 + j] = lm[j];
        }
        __syncthreads();
        if (tid < QT) {
            const int q = tid;
            float mt = sRed[q];
#pragma unroll
            for (int t = 1; t < 16; t++) mt = fmaxf(mt, sRed[t * RDP + q]);
            const float mo = sM[q];
            const float mn = fmaxf(mo, mt);
            sSc[q] = __expf(mo - mn);
            sM[q] = mn;
        }
        __syncthreads();

        // ---- softmax step 2: P = exp(S - m), store P^T, partial sums ----
        {
            float mnj[8];
#pragma unroll
            for (int j = 0; j < 8; j++) mnj[j] = sM[tx*8 + j];
            float ls[8];
#pragma unroll
            for (int j = 0; j < 8; j++) ls[j] = 0.f;
#pragma unroll
            for (int i = 0; i < 8; i++) {
                float p[8];
#pragma unroll
                for (int j = 0; j < 8; j++) {
                    p[j] = __expf(acc[i][j] - mnj[j]);
                    ls[j] += p[j];
                }
                *(float4*)&sPt[(ty*8+i) * PTP + tx*8]     = make_float4(p[0], p[1], p[2], p[3]);
                *(float4*)&sPt[(ty*8+i) * PTP + tx*8 + 4] = make_float4(p[4], p[5], p[6], p[7]);
            }
#pragma unroll
            for (int j = 0; j < 8; j++) sRed[ty * RDP + tx*8 + j] = ls[j];
        }
        __syncthreads();

        // ---- softmax step 3: running sum ----
        if (tid < QT) {
            const int q = tid;
            float s = sRed[q];
#pragma unroll
            for (int t = 1; t < 16; t++) s += sRed[t * RDP + q];
            sL[q] = sL[q] * sSc[q] + s;
        }
        __syncthreads();

        // ---- O tile: rescale then O[q][d] += sum_key P^T[key][q] * V[key][d] ----
        {
            float f[8];
#pragma unroll
            for (int i = 0; i < 8; i++) f[i] = sSc[ty*8 + i];   // broadcast
#pragma unroll
            for (int i = 0; i < 8; i++)
#pragma unroll
                for (int n = 0; n < 4; n++) o[i][n] *= f[i];
        }
#pragma unroll 4
        for (int k = 0; k < KT; k++) {
            float ra[8], rb[4];
            *(float4*)&ra[0] = *(const float4*)&sPt[k * PTP + ty*8];      // broadcast
            *(float4*)&ra[4] = *(const float4*)&sPt[k * PTP + ty*8 + 4];
            *(float4*)&rb[0] = *(const float4*)&sV[k * KVP + tx*4];
#pragma unroll
            for (int i = 0; i < 8; i++)
#pragma unroll
                for (int n = 0; n < 4; n++) o[i][n] += ra[i] * rb[n];
        }
        __syncthreads();   // before next tile overwrites sK/sV/sPt
    }

    // ---- epilogue: normalize and write ----
#pragma unroll
    for (int i = 0; i < 8; i++) {
        const int q = ty*8 + i;
        const float inv = 1.f / sL[q];
        float4 r = make_float4(o[i][0]*inv, o[i][1]*inv, o[i][2]*inv, o[i][3]*inv);
        *(float4*)&g_att[((size_t)(b * S_ + qs + q)) * HID + h * HD + tx*4] = r;
    }
}

// ---------------------------------------------------------------------------
// Output projection: out = att[8192,512] * Wo[512,768] + bo
// ---------------------------------------------------------------------------
__global__ __launch_bounds__(256) void gemm_out(
    const float* __restrict__ Wo, const float* __restrict__ bo,
    float* __restrict__ out)
{
    __shared__ float As[8][128];
    __shared__ float Bs[8][128];

    const int tid = threadIdx.x;
    const int ty = tid >> 4, tx = tid & 15;
    const int rowBase = blockIdx.y * 128;
    const int colBase = blockIdx.x * 128;

    float acc[8][8];
#pragma unroll
    for (int i = 0; i < 8; i++)
#pragma unroll
        for (int j = 0; j < 8; j++) acc[i][j] = 0.f;

    const int arow = tid >> 1, aseg = tid & 1;
    const int brow = tid >> 5, bc4  = tid & 31;

    for (int k0 = 0; k0 < HID; k0 += 8) {
        float4 a = *(const float4*)&g_att[(size_t)(rowBase + arow) * HID + k0 + aseg * 4];
        As[aseg*4+0][arow] = a.x; As[aseg*4+1][arow] = a.y;
        As[aseg*4+2][arow] = a.z; As[aseg*4+3][arow] = a.w;
        float4 bv = *(const float4*)&Wo[(size_t)(k0 + brow) * VD + colBase + bc4 * 4];
        *(float4*)&Bs[brow][bc4 * 4] = bv;
        __syncthreads();
#pragma unroll
        for (int k = 0; k < 8; k++) {
            float ra[8], rb[8];
#pragma unroll
            for (int i = 0; i < 8; i++) ra[i] = As[k][ty * 8 + i];
#pragma unroll
            for (int j = 0; j < 8; j++) rb[j] = Bs[k][tx * 8 + j];
#pragma unroll
            for (int i = 0; i < 8; i++)
#pragma unroll
                for (int j = 0; j < 8; j++) acc[i][j] += ra[i] * rb[j];
        }
        __syncthreads();
    }

#pragma unroll
    for (int i = 0; i < 8; i++) {
        const int m = rowBase + ty * 8 + i;
#pragma unroll
        for (int j = 0; j < 8; j++) {
            const int n = colBase + tx * 8 + j;
            out[(size_t)m * VD + n] = acc[i][j] + bo[n];
        }
    }
}

// ---------------------------------------------------------------------------
extern "C" void kernel_launch(void* const* d_in, const int* in_sizes, int n_in,
                              void* d_out, int out_size)
{
    const float* X  = (const float*)d_in[0];
    const float* Wq = (const float*)d_in[1];
    const float* bq = (const float*)d_in[2];
    const float* Wk = (const float*)d_in[3];
    const float* bk = (const float*)d_in[4];
    const float* Wv = (const float*)d_in[5];
    const float* bv = (const float*)d_in[6];
    const float* Wo = (const float*)d_in[7];
    const float* bo = (const float*)d_in[8];
    float* out = (float*)d_out;

    const size_t attn_smem = ATT2_SMEM_FLOATS * sizeof(float);  // ~181 KB
    cudaFuncSetAttribute(attn_kernel2, cudaFuncAttributeMaxDynamicSharedMemorySize,
                         (int)attn_smem);

    // 1) QKV projections
    {
        dim3 grid(HID / 128, M_ / 128, 3);
        gemm_qkv<<<grid, 256>>>(X, Wq, bq, Wk, bk, Wv, bv);
    }
    // 2) attention
    {
        dim3 grid(S_ / QT, B_ * NH);
        attn_kernel2<<<grid, 256, attn_smem>>>();
    }
    // 3) output projection
    {
        dim3 grid(VD / 128, M_ / 128);
        gemm_out<<<grid, 256>>>(Wo, bo, out);
    }
}

// round 11
// speedup vs baseline: 5.7332x; 2.5658x over previous
#include <cuda_runtime.h>
#include <cuda_bf16.h>
#include <cstdint>

#define B_  4
#define S_  2048
#define TD  768
#define HID 512
#define NH  8
#define HD  64
#define VD  768
#define M_  (B_*S_)   // 8192
#define TDHID (TD*HID)

// Scratch (allocation-free rule: __device__ globals)
__device__ float g_q[B_*NH*S_*HD];
__device__ float g_k[B_*NH*S_*HD];
__device__ float g_v[B_*NH*S_*HD];
__device__ float g_att[M_*HID];
// transposed + split weights: [0..3*TDHID) = Wq,Wk,Wv as [n][k]; [3*TDHID..) = Wo as [n=768][k=512]
__device__ __nv_bfloat16 g_bh[3*TDHID + VD*HID];
__device__ __nv_bfloat16 g_bl[3*TDHID + VD*HID];

struct alignas(8) bf4 { __nv_bfloat16 v[4]; };

__device__ __forceinline__ uint32_t smem_u32(const void* p) {
    uint32_t a;
    asm("{ .reg .u64 t; cvta.to.shared.u64 t, %1; cvt.u32.u64 %0, t; }" : "=r"(a) : "l"(p));
    return a;
}
__device__ __forceinline__ void splitf(float x, __nv_bfloat16& h, __nv_bfloat16& l) {
    h = __float2bfloat16(x);
    l = __float2bfloat16(x - __bfloat162float(h));
}

// ============================ weight prep: transpose + bf16 split ============================
__global__ __launch_bounds__(256) void prep_transpose(const float* __restrict__ W,
                                                      int rows, int cols, int dst_off)
{
    __shared__ float t[32][33];
    const int tx = threadIdx.x & 31, ty = threadIdx.x >> 5;
    const int k0 = blockIdx.x * 32, n0 = blockIdx.y * 32;
#pragma unroll
    for (int j = 0; j < 4; j++) {
        const int k = k0 + ty + j * 8;
        t[ty + j * 8][tx] = W[(size_t)k * cols + n0 + tx];
    }
    __syncthreads();
#pragma unroll
    for (int j = 0; j < 4; j++) {
        const int n = n0 + ty + j * 8;
        const int k = k0 + tx;
        const float x = t[tx][ty + j * 8];
        __nv_bfloat16 h, l; splitf(x, h, l);
        g_bh[dst_off + (size_t)n * rows + k] = h;
        g_bl[dst_off + (size_t)n * rows + k] = l;
    }
}

// ============================ mma.sync helpers ============================
__device__ __forceinline__ void mma16816(float* d, const uint32_t* a, const uint32_t* b)
{
    asm volatile(
        "mma.sync.aligned.m16n8k16.row.col.f32.bf16.bf16.f32 "
        "{%0,%1,%2,%3}, {%4,%5,%6,%7}, {%8,%9}, {%0,%1,%2,%3};"
        : "+f"(d[0]), "+f"(d[1]), "+f"(d[2]), "+f"(d[3])
        : "r"(a[0]), "r"(a[1]), "r"(a[2]), "r"(a[3]), "r"(b[0]), "r"(b[1]));
}
__device__ __forceinline__ void ldmx4t(uint32_t* r, uint32_t addr)
{
    asm volatile("ldmatrix.sync.aligned.m8n8.x4.trans.shared.b16 {%0,%1,%2,%3}, [%4];"
                 : "=r"(r[0]), "=r"(r[1]), "=r"(r[2]), "=r"(r[3]) : "r"(addr));
}

// ============================ mma.sync split-bf16 GEMM (projections) ============================
#define APAD 40

__global__ __launch_bounds__(256) void mma_gemm(
    const float* __restrict__ Aparam, const float* __restrict__ bias,
    float* __restrict__ outp, int ktot, int ntot, int boff, int outsel)
{
    __shared__ __nv_bfloat16 sAh[128 * APAD];
    __shared__ __nv_bfloat16 sAl[128 * APAD];
    __shared__ __nv_bfloat16 sBh[128 * APAD];
    __shared__ __nv_bfloat16 sBl[128 * APAD];

    const int tid = threadIdx.x;
    const int wid = tid >> 5, lid = tid & 31;
    const int wm = wid >> 1, wn = wid & 1;
    const int g = lid >> 2, tg = lid & 3;
    const int rowBase = blockIdx.y * 128;
    const int colBase = blockIdx.x * 128;
    const int nc = ktot / 32;

    const float* A = (outsel == 3) ? (const float*)g_att : Aparam;
    const __nv_bfloat16* Bh = g_bh + boff;
    const __nv_bfloat16* Bl = g_bl + boff;

    float acc[2][8][4];
#pragma unroll
    for (int i = 0; i < 2; i++)
#pragma unroll
        for (int j = 0; j < 8; j++)
#pragma unroll
            for (int r = 0; r < 4; r++) acc[i][j][r] = 0.f;

    for (int c = 0; c < nc; c++) {
        {
            const float* Asrc = A + (size_t)rowBase * ktot + c * 32;
#pragma unroll
            for (int it = 0; it < 4; it++) {
                const int idx = it * 256 + tid;
                const int row = idx >> 3, c4 = idx & 7;
                float4 a = *(const float4*)&Asrc[(size_t)row * ktot + c4 * 4];
                bf4 h, l;
                splitf(a.x, h.v[0], l.v[0]); splitf(a.y, h.v[1], l.v[1]);
                splitf(a.z, h.v[2], l.v[2]); splitf(a.w, h.v[3], l.v[3]);
                *(bf4*)&sAh[row * APAD + c4 * 4] = h;
                *(bf4*)&sAl[row * APAD + c4 * 4] = l;
            }
        }
        {
#pragma unroll
            for (int it = 0; it < 2; it++) {
                const int idx = it * 256 + tid;
                const int n = idx >> 2, c8 = idx & 3;
                const size_t go = (size_t)(colBase + n) * ktot + c * 32 + c8 * 8;
                uint4 vh = *(const uint4*)&Bh[go];
                uint4 vl = *(const uint4*)&Bl[go];
                __nv_bfloat16* dh = &sBh[n * APAD + c8 * 8];
                __nv_bfloat16* dl = &sBl[n * APAD + c8 * 8];
                *(uint2*)(dh)     = make_uint2(vh.x, vh.y);
                *(uint2*)(dh + 4) = make_uint2(vh.z, vh.w);
                *(uint2*)(dl)     = make_uint2(vl.x, vl.y);
                *(uint2*)(dl + 4) = make_uint2(vl.z, vl.w);
            }
        }
        __syncthreads();

#pragma unroll
        for (int ks = 0; ks < 2; ks++) {
            const int k0 = ks * 16 + tg * 2;
            uint32_t ah[2][4], al[2][4];
#pragma unroll
            for (int i = 0; i < 2; i++) {
                const int r0 = wm * 32 + i * 16 + g;
                ah[i][0] = *(const uint32_t*)&sAh[r0 * APAD + k0];
                ah[i][1] = *(const uint32_t*)&sAh[(r0 + 8) * APAD + k0];
                ah[i][2] = *(const uint32_t*)&sAh[r0 * APAD + k0 + 8];
                ah[i][3] = *(const uint32_t*)&sAh[(r0 + 8) * APAD + k0 + 8];
                al[i][0] = *(const uint32_t*)&sAl[r0 * APAD + k0];
                al[i][1] = *(const uint32_t*)&sAl[(r0 + 8) * APAD + k0];
                al[i][2] = *(const uint32_t*)&sAl[r0 * APAD + k0 + 8];
                al[i][3] = *(const uint32_t*)&sAl[(r0 + 8) * APAD + k0 + 8];
            }
#pragma unroll
            for (int j = 0; j < 8; j++) {
                const int n0 = wn * 64 + j * 8 + g;
                uint32_t bh[2], bl[2];
                bh[0] = *(const uint32_t*)&sBh[n0 * APAD + k0];
                bh[1] = *(const uint32_t*)&sBh[n0 * APAD + k0 + 8];
                bl[0] = *(const uint32_t*)&sBl[n0 * APAD + k0];
                bl[1] = *(const uint32_t*)&sBl[n0 * APAD + k0 + 8];
#pragma unroll
                for (int i = 0; i < 2; i++) {
                    mma16816(acc[i][j], ah[i], bh);
                    mma16816(acc[i][j], ah[i], bl);
                    mma16816(acc[i][j], al[i], bh);
                }
            }
        }
        __syncthreads();
    }

    float* oq = (outsel == 0) ? g_q : (outsel == 1) ? g_k : g_v;
#pragma unroll
    for (int i = 0; i < 2; i++) {
        const int m0 = rowBase + wm * 32 + i * 16 + g;
#pragma unroll
        for (int j = 0; j < 8; j++) {
            const int n = colBase + wn * 64 + j * 8 + tg * 2;
            const float bx = __ldg(&bias[n]), by = __ldg(&bias[n + 1]);
            float2 v0 = make_float2(acc[i][j][0] + bx, acc[i][j][1] + by);
            float2 v1 = make_float2(acc[i][j][2] + bx, acc[i][j][3] + by);
            if (outsel < 3) {
                const int h = n >> 6, dd = n & 63;
                const int b0 = m0 >> 11, s0 = m0 & 2047;
                const int m1 = m0 + 8;
                const int b1 = m1 >> 11, s1 = m1 & 2047;
                *(float2*)&oq[(((size_t)(b0 * NH + h) * S_) + s0) * HD + dd] = v0;
                *(float2*)&oq[(((size_t)(b1 * NH + h) * S_) + s1) * HD + dd] = v1;
            } else {
                *(float2*)&outp[(size_t)m0 * ntot + n] = v0;
                *(float2*)&outp[(size_t)(m0 + 8) * ntot + n] = v1;
            }
        }
    }
}

// ============================ FA2-style attention on mma.sync ============================
// Block = one (b,h) x 128 q rows; 8 warps x 16 q rows. Online softmax in registers.
#define VP 72                       // bf16 row stride (64 + 8 pad); 144B = 9*16B
#define TSZ (128*VP)                // 9216 bf16 per tile
#define ASMEM_BYTES (6*TSZ*2)       // 110592

__global__ __launch_bounds__(256, 1) void attn_mma()
{
    extern __shared__ __nv_bfloat16 sm[];
    __nv_bfloat16* sQh = sm;
    __nv_bfloat16* sQl = sm + TSZ;
    __nv_bfloat16* sKh = sm + 2*TSZ;
    __nv_bfloat16* sKl = sm + 3*TSZ;
    __nv_bfloat16* sVh = sm + 4*TSZ;
    __nv_bfloat16* sVl = sm + 5*TSZ;

    const int tid = threadIdx.x, wid = tid >> 5, lid = tid & 31;
    const int g = lid >> 2, tg = lid & 3;
    const int hb = blockIdx.y;
    const int b = hb >> 3, h = hb & 7;
    const int qs = blockIdx.x * 128;

    const size_t headOff = (size_t)(b * NH + h) * S_ * HD;
    const float* Q = g_q + headOff;
    const float* K = g_k + headOff;
    const float* V = g_v + headOff;

    // ---- load Q tile (scaled by 1/8), split hi/lo ----
#pragma unroll
    for (int it = 0; it < 8; it++) {
        const int idx = it * 256 + tid;          // 2048 float4
        const int row = idx >> 4, c4 = idx & 15;
        float4 qv = *(const float4*)&Q[(size_t)(qs + row) * HD + c4 * 4];
        qv.x *= 0.125f; qv.y *= 0.125f; qv.z *= 0.125f; qv.w *= 0.125f;
        bf4 hh, ll;
        splitf(qv.x, hh.v[0], ll.v[0]); splitf(qv.y, hh.v[1], ll.v[1]);
        splitf(qv.z, hh.v[2], ll.v[2]); splitf(qv.w, hh.v[3], ll.v[3]);
        *(bf4*)&sQh[row * VP + c4 * 4] = hh;
        *(bf4*)&sQl[row * VP + c4 * 4] = ll;
    }
    __syncthreads();

    // ---- preload Q A-frags for this warp's 16 rows ----
    const int m0 = wid * 16;
    uint32_t qh[4][4], ql[4][4];
#pragma unroll
    for (int ks = 0; ks < 4; ks++) {
        const int k0 = ks * 16 + tg * 2;
        qh[ks][0] = *(const uint32_t*)&sQh[(m0 + g) * VP + k0];
        qh[ks][1] = *(const uint32_t*)&sQh[(m0 + g + 8) * VP + k0];
        qh[ks][2] = *(const uint32_t*)&sQh[(m0 + g) * VP + k0 + 8];
        qh[ks][3] = *(const uint32_t*)&sQh[(m0 + g + 8) * VP + k0 + 8];
        ql[ks][0] = *(const uint32_t*)&sQl[(m0 + g) * VP + k0];
        ql[ks][1] = *(const uint32_t*)&sQl[(m0 + g + 8) * VP + k0];
        ql[ks][2] = *(const uint32_t*)&sQl[(m0 + g) * VP + k0 + 8];
        ql[ks][3] = *(const uint32_t*)&sQl[(m0 + g + 8) * VP + k0 + 8];
    }

    const uint32_t svh_base = smem_u32(sVh);
    const uint32_t svl_base = smem_u32(sVl);

    float mrow[2] = {-1e30f, -1e30f};
    float lrow[2] = {0.f, 0.f};
    float accO[8][4];
#pragma unroll
    for (int j = 0; j < 8; j++)
#pragma unroll
        for (int r = 0; r < 4; r++) accO[j][r] = 0.f;

    for (int kt = 0; kt < 16; kt++) {
        __syncthreads();   // protect previous iteration's K/V reads
        // ---- load K & V tiles, split hi/lo ----
#pragma unroll
        for (int it = 0; it < 8; it++) {
            const int idx = it * 256 + tid;
            const int row = idx >> 4, c4 = idx & 15;
            float4 kv = *(const float4*)&K[(size_t)(kt * 128 + row) * HD + c4 * 4];
            bf4 hh, ll;
            splitf(kv.x, hh.v[0], ll.v[0]); splitf(kv.y, hh.v[1], ll.v[1]);
            splitf(kv.z, hh.v[2], ll.v[2]); splitf(kv.w, hh.v[3], ll.v[3]);
            *(bf4*)&sKh[row * VP + c4 * 4] = hh;
            *(bf4*)&sKl[row * VP + c4 * 4] = ll;
            float4 vv = *(const float4*)&V[(size_t)(kt * 128 + row) * HD + c4 * 4];
            splitf(vv.x, hh.v[0], ll.v[0]); splitf(vv.y, hh.v[1], ll.v[1]);
            splitf(vv.z, hh.v[2], ll.v[2]); splitf(vv.w, hh.v[3], ll.v[3]);
            *(bf4*)&sVh[row * VP + c4 * 4] = hh;
            *(bf4*)&sVl[row * VP + c4 * 4] = ll;
        }
        __syncthreads();

        // ---- S = Q K^T for this warp's 16 q rows x 128 keys ----
        float accS[16][4];
#pragma unroll
        for (int j = 0; j < 16; j++)
#pragma unroll
            for (int r = 0; r < 4; r++) accS[j][r] = 0.f;

#pragma unroll
        for (int jj = 0; jj < 16; jj++) {
            const int n0 = jj * 8 + g;
#pragma unroll
            for (int ks = 0; ks < 4; ks++) {
                const int k0 = ks * 16 + tg * 2;
                uint32_t bh[2], bl[2];
                bh[0] = *(const uint32_t*)&sKh[n0 * VP + k0];
                bh[1] = *(const uint32_t*)&sKh[n0 * VP + k0 + 8];
                bl[0] = *(const uint32_t*)&sKl[n0 * VP + k0];
                bl[1] = *(const uint32_t*)&sKl[n0 * VP + k0 + 8];
                mma16816(accS[jj], qh[ks], bh);
                mma16816(accS[jj], qh[ks], bl);
                mma16816(accS[jj], ql[ks], bh);
            }
        }

        // ---- online softmax (rows g and g+8 owned by quad lanes) ----
        float alpha[2];
#pragma unroll
        for (int r = 0; r < 2; r++) {
            float mt = -1e30f;
#pragma unroll
            for (int jj = 0; jj < 16; jj++)
                mt = fmaxf(mt, fmaxf(accS[jj][2*r], accS[jj][2*r+1]));
            mt = fmaxf(mt, __shfl_xor_sync(0xffffffffu, mt, 1));
            mt = fmaxf(mt, __shfl_xor_sync(0xffffffffu, mt, 2));
            const float mn = fmaxf(mrow[r], mt);
            alpha[r] = __expf(mrow[r] - mn);
            mrow[r] = mn;
        }
        float ls0 = 0.f, ls1 = 0.f;
#pragma unroll
        for (int jj = 0; jj < 16; jj++) {
            float p0 = __expf(accS[jj][0] - mrow[0]);
            float p1 = __expf(accS[jj][1] - mrow[0]);
            float p2 = __expf(accS[jj][2] - mrow[1]);
            float p3 = __expf(accS[jj][3] - mrow[1]);
            accS[jj][0] = p0; accS[jj][1] = p1; accS[jj][2] = p2; accS[jj][3] = p3;
            ls0 += p0 + p1; ls1 += p2 + p3;
        }
        ls0 += __shfl_xor_sync(0xffffffffu, ls0, 1);
        ls0 += __shfl_xor_sync(0xffffffffu, ls0, 2);
        ls1 += __shfl_xor_sync(0xffffffffu, ls1, 1);
        ls1 += __shfl_xor_sync(0xffffffffu, ls1, 2);
        lrow[0] = lrow[0] * alpha[0] + ls0;
        lrow[1] = lrow[1] * alpha[1] + ls1;
#pragma unroll
        for (int j = 0; j < 8; j++) {
            accO[j][0] *= alpha[0]; accO[j][1] *= alpha[0];
            accO[j][2] *= alpha[1]; accO[j][3] *= alpha[1];
        }

        // ---- O += P V ----
        const int lr = lid & 7, sel = lid >> 3;
        const int rofs = ((sel & 1) ? 8 : 0) + lr;
        const int cofs = (sel & 2) ? 8 : 0;
#pragma unroll
        for (int kk = 0; kk < 8; kk++) {
            // pack P A-frags (hi/lo) from accS[2kk], accS[2kk+1]
            uint32_t pah[4], pal[4];
            {
                const float* s0 = accS[2*kk];
                const float* s1 = accS[2*kk + 1];
                __nv_bfloat16 h0, l0, h1, l1;
                splitf(s0[0], h0, l0); splitf(s0[1], h1, l1);
                pah[0] = ((uint32_t)*(uint16_t*)&h1 << 16) | *(uint16_t*)&h0;
                pal[0] = ((uint32_t)*(uint16_t*)&l1 << 16) | *(uint16_t*)&l0;
                splitf(s0[2], h0, l0); splitf(s0[3], h1, l1);
                pah[1] = ((uint32_t)*(uint16_t*)&h1 << 16) | *(uint16_t*)&h0;
                pal[1] = ((uint32_t)*(uint16_t*)&l1 << 16) | *(uint16_t*)&l0;
                splitf(s1[0], h0, l0); splitf(s1[1], h1, l1);
                pah[2] = ((uint32_t)*(uint16_t*)&h1 << 16) | *(uint16_t*)&h0;
                pal[2] = ((uint32_t)*(uint16_t*)&l1 << 16) | *(uint16_t*)&l0;
                splitf(s1[2], h0, l0); splitf(s1[3], h1, l1);
                pah[3] = ((uint32_t)*(uint16_t*)&h1 << 16) | *(uint16_t*)&h0;
                pal[3] = ((uint32_t)*(uint16_t*)&l1 << 16) | *(uint16_t*)&l0;
            }
            const int k0 = kk * 16;
#pragma unroll
            for (int dn = 0; dn < 4; dn++) {
                const int d0 = dn * 16;
                const uint32_t ah_addr = svh_base + (uint32_t)((k0 + rofs) * VP + d0 + cofs) * 2;
                const uint32_t al_addr = svl_base + (uint32_t)((k0 + rofs) * VP + d0 + cofs) * 2;
                uint32_t vh[4], vl[4];
                ldmx4t(vh, ah_addr);
                ldmx4t(vl, al_addr);
                mma16816(accO[dn*2],     pah, &vh[0]);
                mma16816(accO[dn*2],     pah, &vl[0]);
                mma16816(accO[dn*2],     pal, &vh[0]);
                mma16816(accO[dn*2 + 1], pah, &vh[2]);
                mma16816(accO[dn*2 + 1], pah, &vl[2]);
                mma16816(accO[dn*2 + 1], pal, &vh[2]);
            }
        }
    }

    // ---- epilogue: normalize, write head-major ----
    const float inv0 = 1.f / lrow[0];
    const float inv1 = 1.f / lrow[1];
    const int q0 = qs + m0 + g;
#pragma unroll
    for (int j = 0; j < 8; j++) {
        const int d = h * HD + j * 8 + tg * 2;
        *(float2*)&g_att[((size_t)(b * S_ + q0)) * HID + d] =
            make_float2(accO[j][0] * inv0, accO[j][1] * inv0);
        *(float2*)&g_att[((size_t)(b * S_ + q0 + 8)) * HID + d] =
            make_float2(accO[j][2] * inv1, accO[j][3] * inv1);
    }
}

// ---------------------------------------------------------------------------
extern "C" void kernel_launch(void* const* d_in, const int* in_sizes, int n_in,
                              void* d_out, int out_size)
{
    const float* X  = (const float*)d_in[0];
    const float* Wq = (const float*)d_in[1];
    const float* bq = (const float*)d_in[2];
    const float* Wk = (const float*)d_in[3];
    const float* bk = (const float*)d_in[4];
    const float* Wv = (const float*)d_in[5];
    const float* bv = (const float*)d_in[6];
    const float* Wo = (const float*)d_in[7];
    const float* bo = (const float*)d_in[8];
    float* out = (float*)d_out;

    cudaFuncSetAttribute(attn_mma, cudaFuncAttributeMaxDynamicSharedMemorySize,
                         ASMEM_BYTES);

    // 0) weight prep
    prep_transpose<<<dim3(TD/32, HID/32), 256>>>(Wq, TD, HID, 0 * TDHID);
    prep_transpose<<<dim3(TD/32, HID/32), 256>>>(Wk, TD, HID, 1 * TDHID);
    prep_transpose<<<dim3(TD/32, HID/32), 256>>>(Wv, TD, HID, 2 * TDHID);
    prep_transpose<<<dim3(HID/32, VD/32), 256>>>(Wo, HID, VD, 3 * TDHID);

    // 1) QKV projections (mma.sync split-bf16)
    mma_gemm<<<dim3(HID/128, M_/128), 256>>>(X, bq, nullptr, TD, HID, 0 * TDHID, 0);
    mma_gemm<<<dim3(HID/128, M_/128), 256>>>(X, bk, nullptr, TD, HID, 1 * TDHID, 1);
    mma_gemm<<<dim3(HID/128, M_/128), 256>>>(X, bv, nullptr, TD, HID, 2 * TDHID, 2);

    // 2) attention (FA2-style mma.sync)
    attn_mma<<<dim3(S_/128, B_*NH), 256, ASMEM_BYTES>>>();

    // 3) output projection
    mma_gemm<<<dim3(VD/128, M_/128), 256>>>(X, bo, out, HID, VD, 3 * TDHID, 3);
}